// round 15
// baseline (speedup 1.0000x reference)
#include <cuda_runtime.h>
#include <cuda_bf16.h>
#include <cstdint>

#define T_STEPS 512
#define BATCH   128
#define DIM     512
#define M_ROWS  (T_STEPS * BATCH)   // 65536

typedef unsigned long long u64;

// Scratch
__device__ float g_xproj[(size_t)T_STEPS * BATCH * DIM];        // 134 MB
__device__ __nv_bfloat16 g_Xhi[(size_t)M_ROWS * DIM];           // 67 MB
__device__ __nv_bfloat16 g_Xlo[(size_t)M_ROWS * DIM];           // 67 MB
__device__ __nv_bfloat16 g_Whi[DIM * DIM];
__device__ __nv_bfloat16 g_Wlo[DIM * DIM];

// L2 h-exchange images: [buf][group][16640 bytes] (same layout as smem hc)
#define HC_BSTRIDE  2080
#define HC_BUF      16640
__device__ __align__(16) char g_hx[2][16][HC_BUF];              // 532 KB

// ---------------------------------------------------------------------------
// helpers
// ---------------------------------------------------------------------------
__device__ __forceinline__ void split2(float x, float y,
                                       uint32_t& hi, uint32_t& lo) {
    __nv_bfloat16 hx = __float2bfloat16(x), hy = __float2bfloat16(y);
    float rx = x - __bfloat162float(hx);
    float ry = y - __bfloat162float(hy);
    __nv_bfloat162 h2(hx, hy);
    __nv_bfloat162 l2(__float2bfloat16(rx), __float2bfloat16(ry));
    hi = *reinterpret_cast<uint32_t*>(&h2);
    lo = *reinterpret_cast<uint32_t*>(&l2);
}
__device__ __forceinline__ u64 cellpack(float a, float b) {
    uint32_t hi, lo;
    split2(a, b, hi, lo);
    return (u64)hi | ((u64)lo << 32);
}

// mbarrier helpers (baseline sm_90 family)
__device__ __forceinline__ void mbar_init(uint32_t mb, uint32_t cnt) {
    asm volatile("mbarrier.init.shared.b64 [%0], %1;" :: "r"(mb), "r"(cnt)
                 : "memory");
}
__device__ __forceinline__ void mbar_wait_parity(uint32_t mb, uint32_t par) {
    uint32_t done;
    asm volatile(
        "{\n\t.reg .pred p;\n\t"
        "mbarrier.try_wait.parity.acquire.cta.shared::cta.b64 p, [%1], %2;\n\t"
        "selp.b32 %0, 1, 0, p;\n\t}"
        : "=r"(done) : "r"(mb), "r"(par) : "memory");
    if (!done) {
        asm volatile(
            "{\n\t.reg .pred P1;\n\t"
            "WAIT_LOOP_%=:\n\t"
            "mbarrier.try_wait.parity.acquire.cta.shared::cta.b64 P1, [%0], %1, 0x989680;\n\t"
            "@P1 bra.uni WAIT_DONE_%=;\n\t"
            "bra.uni WAIT_LOOP_%=;\n\t"
            "WAIT_DONE_%=:\n\t}"
            :: "r"(mb), "r"(par) : "memory");
    }
}
// arrive on rank rr's copy of the mbarrier at local smem address mb
__device__ __forceinline__ void mbar_arrive_rank(uint32_t mb, int rr) {
    asm volatile(
        "{\n\t.reg .b32 ra;\n\t"
        "mapa.shared::cluster.u32 ra, %0, %1;\n\t"
        "mbarrier.arrive.shared::cluster.b64 _, [ra];\n\t}"
        :: "r"(mb), "r"(rr) : "memory");
}
#define FENCE_GPU() asm volatile("fence.acq_rel.gpu;" ::: "memory")

// mma.sync / ldmatrix (sm_80+ baseline; validated R11/R13/R14)
__device__ __forceinline__ void ldsm_x4(uint32_t& r0, uint32_t& r1,
                                        uint32_t& r2, uint32_t& r3,
                                        uint32_t addr) {
    asm volatile("ldmatrix.sync.aligned.m8n8.x4.shared.b16 {%0,%1,%2,%3}, [%4];"
                 : "=r"(r0), "=r"(r1), "=r"(r2), "=r"(r3) : "r"(addr));
}
__device__ __forceinline__ void mma16816(float* d, const uint32_t* a,
                                         const uint32_t* b) {
    asm volatile(
        "mma.sync.aligned.m16n8k16.row.col.f32.bf16.bf16.f32 "
        "{%0,%1,%2,%3}, {%4,%5,%6,%7}, {%8,%9}, {%0,%1,%2,%3};"
        : "+f"(d[0]), "+f"(d[1]), "+f"(d[2]), "+f"(d[3])
        : "r"(a[0]), "r"(a[1]), "r"(a[2]), "r"(a[3]), "r"(b[0]), "r"(b[1]));
}
#define SWZ128(o) ((o) ^ (((o) >> 3) & 0x70))

// ============================================================================
// Kernel 0: fp32 -> bf16 hi/lo split
// ============================================================================
__global__ void split_kernel(const float* __restrict__ src,
                             __nv_bfloat162* __restrict__ hi,
                             __nv_bfloat162* __restrict__ lo, int n4) {
    int i = blockIdx.x * 256 + threadIdx.x;
    if (i >= n4) return;
    float4 v = ((const float4*)src)[i];
    uint32_t h0, l0, h1, l1;
    split2(v.x, v.y, h0, l0);
    split2(v.z, v.w, h1, l1);
    *(uint32_t*)&hi[i * 2 + 0] = h0;
    *(uint32_t*)&hi[i * 2 + 1] = h1;
    *(uint32_t*)&lo[i * 2 + 0] = l0;
    *(uint32_t*)&lo[i * 2 + 1] = l1;
}

// ============================================================================
// Kernel 1: Xproj via mma.sync bf16 3-split — UNCHANGED (validated R11-R14).
// ============================================================================
#define SM_AHI 0
#define SM_ALO 16384
#define SM_WHI 32768
#define SM_WLO 49152
#define GEMM2_SMEM 65536

__global__ void __launch_bounds__(256, 2)
xproj_mma(const __nv_bfloat16* __restrict__ Xhi,
          const __nv_bfloat16* __restrict__ Xlo,
          const __nv_bfloat16* __restrict__ Whi,
          const __nv_bfloat16* __restrict__ Wlo) {
    extern __shared__ __align__(1024) char sm[];
    const uint32_t smb = (uint32_t)__cvta_generic_to_shared(sm);
    const int tid  = threadIdx.x;
    const int lane = tid & 31;
    const int w    = tid >> 5;
    const int n0 = blockIdx.x * 128;
    const int m0 = blockIdx.y * 128;
    const int m_w = (w & 3) * 32;
    const int n_w = (w >> 2) * 64;

    float acc[2][8][4];
#pragma unroll
    for (int i = 0; i < 2; i++)
#pragma unroll
        for (int j = 0; j < 8; j++)
#pragma unroll
            for (int q = 0; q < 4; q++) acc[i][j][q] = 0.0f;

    const __nv_bfloat16* srcs[4] = {
        Xhi + (size_t)m0 * 512, Xlo + (size_t)m0 * 512,
        Whi + (size_t)n0 * 512, Wlo + (size_t)n0 * 512 };
    const uint32_t tgt_off[4] = { SM_AHI, SM_ALO, SM_WHI, SM_WLO };

    const int a_row_l = lane & 15;
    const int a_x_l   = (lane >> 4) * 16;
    const int b_row_l = ((lane >> 4) & 1) * 8 + (lane & 7);
    const int b_x_l   = ((lane >> 3) & 1) * 16;

    for (int c = 0; c < 8; c++) {
        const int kc = c * 64;
#pragma unroll
        for (int tgt = 0; tgt < 4; tgt++) {
#pragma unroll
            for (int i = 0; i < 4; i++) {
                const int idx = tid + i * 256;
                const int row = idx >> 3;
                const int cb  = (idx & 7) * 16;
                const char* gp =
                    (const char*)(srcs[tgt] + (size_t)row * 512 + kc) + cb;
                uint4 v = *(const uint4*)gp;
                uint32_t off = (uint32_t)(row * 128 + cb);
                *(uint4*)(sm + tgt_off[tgt] + SWZ128(off)) = v;
            }
        }
        __syncthreads();

#pragma unroll
        for (int sp = 0; sp < 3; sp++) {
            const uint32_t abase = smb + (sp == 1 ? SM_ALO : SM_AHI);
            const uint32_t bbase = smb + (sp == 2 ? SM_WLO : SM_WHI);
#pragma unroll
            for (int ks = 0; ks < 4; ks++) {
                uint32_t afr[2][4];
#pragma unroll
                for (int mb = 0; mb < 2; mb++) {
                    const int row = m_w + mb * 16 + a_row_l;
                    const int x   = a_x_l + ks * 32;
                    uint32_t off = (uint32_t)(row * 128 +
                                              (x ^ ((row & 7) << 4)));
                    ldsm_x4(afr[mb][0], afr[mb][1], afr[mb][2], afr[mb][3],
                            abase + off);
                }
                uint32_t bfr[8][2];
#pragma unroll
                for (int pb = 0; pb < 4; pb++) {
                    const int row = n_w + pb * 16 + b_row_l;
                    const int x   = b_x_l + ks * 32;
                    uint32_t off = (uint32_t)(row * 128 +
                                              (x ^ ((row & 7) << 4)));
                    uint32_t r0, r1, r2, r3;
                    ldsm_x4(r0, r1, r2, r3, bbase + off);
                    bfr[pb * 2 + 0][0] = r0; bfr[pb * 2 + 0][1] = r1;
                    bfr[pb * 2 + 1][0] = r2; bfr[pb * 2 + 1][1] = r3;
                }
#pragma unroll
                for (int mb = 0; mb < 2; mb++)
#pragma unroll
                    for (int nb = 0; nb < 8; nb++)
                        mma16816(acc[mb][nb], afr[mb], bfr[nb]);
            }
        }
        __syncthreads();
    }

    const int rbase = m0 + m_w + (lane >> 2);
    const int cbase = n0 + n_w + (lane & 3) * 2;
#pragma unroll
    for (int mb = 0; mb < 2; mb++) {
#pragma unroll
        for (int nb = 0; nb < 8; nb++) {
            float* p0 = g_xproj + (size_t)(rbase + mb * 16) * 512 + cbase + nb * 8;
            float* p1 = p0 + 8 * 512;
            *(float2*)p0 = make_float2(acc[mb][nb][0], acc[mb][nb][1]);
            *(float2*)p1 = make_float2(acc[mb][nb][2], acc[mb][nb][3]);
        }
    }
}

// ============================================================================
// Kernel 2: recurrent scan via mma.sync, register-resident W_h (R14 base).
// R15 delta: DSMEM st.async push (2048 scattered 8B stores/CTA/step)
// replaced by L2 exchange: producers STG 4x u64 to g_hx[q][g]; one thread
// fences + posts 8 cluster mbarrier arrivals (count=8); consumers wake,
// fence, bulk-copy the 16.6KB image to smem (LDG.128, L2-resident).
// hc is now single-buffered (copy-in each step).
// ============================================================================
#define STG_OFF     HC_BUF               // 16640 (16-aligned)
#define MBAR_OFF2   (STG_OFF + 2048)     // 18688
#define SCAN_SMEM   (MBAR_OFF2 + 16)

__device__ __forceinline__ int rowoff(int b) {
    return b * HC_BSTRIDE;
}

__global__ void __cluster_dims__(8, 1, 1) __launch_bounds__(256, 1)
rnn_scan(const float* __restrict__ Wh, const float* __restrict__ bh,
         float* __restrict__ out) {
    extern __shared__ __align__(16) char sm[];
    char*  hc  = sm;                          // [HC_BUF] h cells (single buf)
    float* stg = (float*)(sm + STG_OFF);      // [4][32] float4 staging

    const int tid   = threadIdx.x;
    const int lane  = tid & 31;
    const int w     = tid >> 5;
    const int j     = w >> 1;        // m-block 0..3
    const int kh    = w & 1;         // k-half
    const int rk    = blockIdx.x & 7;    // cluster rank -> dim slice
    const int g     = blockIdx.x >> 3;   // batch group
    const int row_l = lane >> 2;     // 0..7 (A-row low / B-n)
    const int qb    = lane & 3;

    const uint32_t smb     = (uint32_t)__cvta_generic_to_shared(sm);
    const uint32_t mb_u32  = smb + MBAR_OFF2;

    const int d_base = rk * 64 + j * 16;

    // ---- W_h fragments into registers (bf16 hi/lo split), one-time ----
    uint32_t whi[16][4], wlo[16][4];
    {
        const float* Wr0 = Wh + (size_t)(d_base + row_l) * 512 + kh * 256;
        const float* Wr1 = Wr0 + 8 * 512;
#pragma unroll
        for (int ks = 0; ks < 16; ks++) {
            const int k0 = ks * 16 + qb * 2;
            float2 q00 = *(const float2*)(Wr0 + k0);
            float2 q10 = *(const float2*)(Wr1 + k0);
            float2 q01 = *(const float2*)(Wr0 + k0 + 8);
            float2 q11 = *(const float2*)(Wr1 + k0 + 8);
            split2(q00.x, q00.y, whi[ks][0], wlo[ks][0]);
            split2(q10.x, q10.y, whi[ks][1], wlo[ks][1]);
            split2(q01.x, q01.y, whi[ks][2], wlo[ks][2]);
            split2(q11.x, q11.y, whi[ks][3], wlo[ks][3]);
        }
    }

    // ---- zero hc (t=0 reads zeros) ----
    for (int i = tid; i < HC_BUF / 8; i += 256) ((u64*)hc)[i] = 0ull;
    if (tid == 0) {
        mbar_init(mb_u32 + 0, 8);   // arrival-count: one per CTA
        mbar_init(mb_u32 + 8, 8);
    }
    __syncthreads();
    // mbarriers valid cluster-wide before any remote arrive
    asm volatile("barrier.cluster.arrive.aligned;" ::: "memory");
    asm volatile("barrier.cluster.wait.aligned;"   ::: "memory");

    // ---- B-frag read base: batch row = row_l, k-pair = kh*128 + ks*8 + qb --
    const char* hbase = hc + rowoff(row_l) + (kh * 128 + qb) * 8;

    // ---- output/push mapping (even warps own final D after reduce) ----
    const int b0l   = qb * 2;                     // local batch pair
    const int bgl0  = g * 8 + b0l;
    const float bias0 = bh[d_base + row_l];
    const float bias1 = bh[d_base + row_l + 8];
    const float* xpb = g_xproj + ((size_t)bgl0 * 512 + d_base + row_l);

    // L2 push base for this producer's cells: (b0l, dpA)
    const int dpA = rk * 32 + j * 8 + (row_l >> 1);
    const int push_off = rowoff(b0l) + dpA * 8;

    // prefetch xp(0)
    float xq0 = 0.f, xq1 = 0.f, xq2 = 0.f, xq3 = 0.f;
    if (!kh) {
        xq0 = __ldg(xpb);        xq1 = __ldg(xpb + 512);
        xq2 = __ldg(xpb + 8);    xq3 = __ldg(xpb + 520);
    }

    uint32_t ph0 = 0, ph1 = 0;

    for (int t = 0; t < T_STEPS; t++) {
        const int p = t & 1;

        if (t > 0) {
            // wait for 8 arrivals (all CTAs' step-(t-1) data in g_hx[p])
            const uint32_t mb = mb_u32 + (uint32_t)p * 8;
            mbar_wait_parity(mb, p ? ph1 : ph0);
            if (p) ph1 ^= 1; else ph0 ^= 1;
            FENCE_GPU();
            // bulk copy L2 image -> smem (1040 x 16B, L2-resident)
            {
                const float4* s4 = (const float4*)(g_hx[p][g]);
                float4* d4 = (float4*)hc;
                for (int i = tid; i < HC_BUF / 16; i += 256)
                    d4[i] = __ldcg(s4 + i);
            }
            __syncthreads();
        }

        // ---- mma over this warp's k-half: THREE independent chains ----
        float da[4] = {0.f, 0.f, 0.f, 0.f};   // whi * h_hi
        float db[4] = {0.f, 0.f, 0.f, 0.f};   // wlo * h_hi
        float dc[4] = {0.f, 0.f, 0.f, 0.f};   // whi * h_lo
#pragma unroll
        for (int ks = 0; ks < 16; ks++) {
            const char* cp = hbase + ks * 64;
            uint32_t bhv[2], blv[2];
            bhv[0] = *(const uint32_t*)(cp);
            blv[0] = *(const uint32_t*)(cp + 4);
            bhv[1] = *(const uint32_t*)(cp + 32);
            blv[1] = *(const uint32_t*)(cp + 36);
            mma16816(da, whi[ks], bhv);
            mma16816(db, wlo[ks], bhv);
            mma16816(dc, whi[ks], blv);
        }
        float dacc[4];
#pragma unroll
        for (int q = 0; q < 4; q++) dacc[q] = (da[q] + db[q]) + dc[q];

        // ---- k-half pair reduce via staging ----
        if (kh) {
            ((float4*)stg)[j * 32 + lane] =
                make_float4(dacc[0], dacc[1], dacc[2], dacc[3]);
        }
        __syncthreads();

        if (!kh) {
            float4 o = ((float4*)stg)[j * 32 + lane];
            const float z0 = dacc[0] + o.x + xq0 + bias0;  // (r,   b0)
            const float z1 = dacc[1] + o.y + xq1 + bias0;  // (r,   b1)
            const float z2 = dacc[2] + o.z + xq2 + bias1;  // (r+8, b0)
            const float z3 = dacc[3] + o.w + xq3 + bias1;
            const float h0 = 1.0f / (1.0f + __expf(-z0));
            const float h1 = 1.0f / (1.0f + __expf(-z1));
            const float h2 = 1.0f / (1.0f + __expf(-z2));
            const float h3 = 1.0f / (1.0f + __expf(-z3));

            if (t < T_STEPS - 1) {
                // partner (d+1) values live at lane+4 (row_l+1)
                const float n0 = __shfl_down_sync(0xffffffffu, h0, 4);
                const float n1 = __shfl_down_sync(0xffffffffu, h1, 4);
                const float n2 = __shfl_down_sync(0xffffffffu, h2, 4);
                const float n3 = __shfl_down_sync(0xffffffffu, h3, 4);
                if (!(row_l & 1)) {
                    char* d0 = g_hx[p ^ 1][g] + push_off;
                    *(u64*)(d0)                    = cellpack(h0, n0);
                    *(u64*)(d0 + HC_BSTRIDE)       = cellpack(h1, n1);
                    *(u64*)(d0 + 32)               = cellpack(h2, n2);
                    *(u64*)(d0 + HC_BSTRIDE + 32)  = cellpack(h3, n3);
                }
                // prefetch xp(t+1)
                const float* xn = xpb + (size_t)(t + 1) * BATCH * DIM;
                xq0 = __ldg(xn);      xq1 = __ldg(xn + 512);
                xq2 = __ldg(xn + 8);  xq3 = __ldg(xn + 520);
            } else {
                float* ob = out + (size_t)bgl0 * 512 + d_base + row_l;
                ob[0]       = h0;
                ob[512]     = h1;
                ob[8]       = h2;
                ob[520]     = h3;
            }
        }
        __syncthreads();   // all producer STGs program-ordered before fence

        if (t < T_STEPS - 1 && tid == 0) {
            FENCE_GPU();   // cumulative: covers all threads' STGs (post-sync)
            const uint32_t mbq = mb_u32 + (uint32_t)((p ^ 1) * 8);
#pragma unroll
            for (int rr = 0; rr < 8; rr++) mbar_arrive_rank(mbq, rr);
        }
    }

    // keep cluster alive for in-flight remote arrivals
    asm volatile("barrier.cluster.arrive.aligned;" ::: "memory");
    asm volatile("barrier.cluster.wait.aligned;"   ::: "memory");
}

// ============================================================================
extern "C" void kernel_launch(void* const* d_in, const int* in_sizes, int n_in,
                              void* d_out, int out_size) {
    const float* X    = (const float*)d_in[0];  // [512,128,512]
    const float* W_in = (const float*)d_in[1];  // [512,512]
    const float* W_h  = (const float*)d_in[2];  // [512,512]
    const float* b_h  = (const float*)d_in[3];  // [512]
    float* out = (float*)d_out;                 // [128,512]

    (void)in_sizes; (void)n_in; (void)out_size;

    __nv_bfloat162 *xhi, *xlo, *whi, *wlo;
    cudaGetSymbolAddress((void**)&xhi, g_Xhi);
    cudaGetSymbolAddress((void**)&xlo, g_Xlo);
    cudaGetSymbolAddress((void**)&whi, g_Whi);
    cudaGetSymbolAddress((void**)&wlo, g_Wlo);

    // 0) split X and W_in into bf16 hi/lo
    split_kernel<<<(M_ROWS * DIM / 4 + 255) / 256, 256>>>(X, xhi, xlo,
                                                          M_ROWS * DIM / 4);
    split_kernel<<<(DIM * DIM / 4 + 255) / 256, 256>>>(W_in, whi, wlo,
                                                       DIM * DIM / 4);

    // 1) Xproj via mma.sync bf16 (3-split)
    cudaFuncSetAttribute(xproj_mma,
                         cudaFuncAttributeMaxDynamicSharedMemorySize,
                         GEMM2_SMEM);
    dim3 g1(DIM / 128, M_ROWS / 128);   // (4, 512)
    xproj_mma<<<g1, 256, GEMM2_SMEM>>>(
        (const __nv_bfloat16*)xhi, (const __nv_bfloat16*)xlo,
        (const __nv_bfloat16*)whi, (const __nv_bfloat16*)wlo);

    // 2) recurrent scan via mma.sync (register-resident W_h, L2 exchange)
    rnn_scan<<<128, 256, SCAN_SMEM>>>(W_h, b_h, out);
}

// round 16
// speedup vs baseline: 2.5535x; 2.5535x over previous
#include <cuda_runtime.h>
#include <cuda_bf16.h>
#include <cstdint>

#define T_STEPS 512
#define BATCH   128
#define DIM     512
#define M_ROWS  (T_STEPS * BATCH)   // 65536

typedef unsigned long long u64;

// Scratch
__device__ float g_xproj[(size_t)T_STEPS * BATCH * DIM];        // 134 MB
__device__ __nv_bfloat16 g_Xhi[(size_t)M_ROWS * DIM];           // 67 MB
__device__ __nv_bfloat16 g_Xlo[(size_t)M_ROWS * DIM];           // 67 MB
__device__ __nv_bfloat16 g_Whi[DIM * DIM];
__device__ __nv_bfloat16 g_Wlo[DIM * DIM];

// ---------------------------------------------------------------------------
// helpers
// ---------------------------------------------------------------------------
__device__ __forceinline__ void split2(float x, float y,
                                       uint32_t& hi, uint32_t& lo) {
    __nv_bfloat16 hx = __float2bfloat16(x), hy = __float2bfloat16(y);
    float rx = x - __bfloat162float(hx);
    float ry = y - __bfloat162float(hy);
    __nv_bfloat162 h2(hx, hy);
    __nv_bfloat162 l2(__float2bfloat16(rx), __float2bfloat16(ry));
    hi = *reinterpret_cast<uint32_t*>(&h2);
    lo = *reinterpret_cast<uint32_t*>(&l2);
}
// pack 4 bf16: {a,b} (batch b0) and {c,d} (batch b1) into one u64
__device__ __forceinline__ u64 pack4bf(float a, float b, float c, float d) {
    __nv_bfloat162 p0(__float2bfloat16(a), __float2bfloat16(b));
    __nv_bfloat162 p1(__float2bfloat16(c), __float2bfloat16(d));
    uint32_t u0 = *reinterpret_cast<uint32_t*>(&p0);
    uint32_t u1 = *reinterpret_cast<uint32_t*>(&p1);
    return (u64)u0 | ((u64)u1 << 32);
}

// mbarrier / st.async (baseline features, proven R9/R11/R13/R14)
__device__ __forceinline__ void mbar_init(uint32_t mb, uint32_t cnt) {
    asm volatile("mbarrier.init.shared.b64 [%0], %1;" :: "r"(mb), "r"(cnt)
                 : "memory");
}
__device__ __forceinline__ void mbar_expect_tx(uint32_t mb, uint32_t bytes) {
    asm volatile("mbarrier.arrive.expect_tx.shared.b64 _, [%0], %1;"
                 :: "r"(mb), "r"(bytes) : "memory");
}
__device__ __forceinline__ void mbar_wait_parity(uint32_t mb, uint32_t par) {
    uint32_t done;
    asm volatile(
        "{\n\t.reg .pred p;\n\t"
        "mbarrier.try_wait.parity.acquire.cta.shared::cta.b64 p, [%1], %2;\n\t"
        "selp.b32 %0, 1, 0, p;\n\t}"
        : "=r"(done) : "r"(mb), "r"(par) : "memory");
    if (!done) {
        asm volatile(
            "{\n\t.reg .pred P1;\n\t"
            "WAIT_LOOP_%=:\n\t"
            "mbarrier.try_wait.parity.acquire.cta.shared::cta.b64 P1, [%0], %1, 0x989680;\n\t"
            "@P1 bra.uni WAIT_DONE_%=;\n\t"
            "bra.uni WAIT_LOOP_%=;\n\t"
            "WAIT_DONE_%=:\n\t}"
            :: "r"(mb), "r"(par) : "memory");
    }
}
__device__ __forceinline__ void st_async_cluster_u64(uint32_t dst, u64 val,
                                                     uint32_t rmb) {
    asm volatile(
        "st.async.shared::cluster.mbarrier::complete_tx::bytes.b64 [%0], %1, [%2];"
        :: "r"(dst), "l"(val), "r"(rmb) : "memory");
}

// mma.sync / ldmatrix (sm_80+ baseline; validated R11/R13/R14)
__device__ __forceinline__ void ldsm_x4(uint32_t& r0, uint32_t& r1,
                                        uint32_t& r2, uint32_t& r3,
                                        uint32_t addr) {
    asm volatile("ldmatrix.sync.aligned.m8n8.x4.shared.b16 {%0,%1,%2,%3}, [%4];"
                 : "=r"(r0), "=r"(r1), "=r"(r2), "=r"(r3) : "r"(addr));
}
__device__ __forceinline__ void mma16816(float* d, const uint32_t* a,
                                         const uint32_t* b) {
    asm volatile(
        "mma.sync.aligned.m16n8k16.row.col.f32.bf16.bf16.f32 "
        "{%0,%1,%2,%3}, {%4,%5,%6,%7}, {%8,%9}, {%0,%1,%2,%3};"
        : "+f"(d[0]), "+f"(d[1]), "+f"(d[2]), "+f"(d[3])
        : "r"(a[0]), "r"(a[1]), "r"(a[2]), "r"(a[3]), "r"(b[0]), "r"(b[1]));
}
#define SWZ128(o) ((o) ^ (((o) >> 3) & 0x70))

// ============================================================================
// Kernel 0: fp32 -> bf16 hi/lo split
// ============================================================================
__global__ void split_kernel(const float* __restrict__ src,
                             __nv_bfloat162* __restrict__ hi,
                             __nv_bfloat162* __restrict__ lo, int n4) {
    int i = blockIdx.x * 256 + threadIdx.x;
    if (i >= n4) return;
    float4 v = ((const float4*)src)[i];
    uint32_t h0, l0, h1, l1;
    split2(v.x, v.y, h0, l0);
    split2(v.z, v.w, h1, l1);
    *(uint32_t*)&hi[i * 2 + 0] = h0;
    *(uint32_t*)&hi[i * 2 + 1] = h1;
    *(uint32_t*)&lo[i * 2 + 0] = l0;
    *(uint32_t*)&lo[i * 2 + 1] = l1;
}

// ============================================================================
// Kernel 1: Xproj via mma.sync bf16 3-split — UNCHANGED (validated R11-R14).
// ============================================================================
#define SM_AHI 0
#define SM_ALO 16384
#define SM_WHI 32768
#define SM_WLO 49152
#define GEMM2_SMEM 65536

__global__ void __launch_bounds__(256, 2)
xproj_mma(const __nv_bfloat16* __restrict__ Xhi,
          const __nv_bfloat16* __restrict__ Xlo,
          const __nv_bfloat16* __restrict__ Whi,
          const __nv_bfloat16* __restrict__ Wlo) {
    extern __shared__ __align__(1024) char sm[];
    const uint32_t smb = (uint32_t)__cvta_generic_to_shared(sm);
    const int tid  = threadIdx.x;
    const int lane = tid & 31;
    const int w    = tid >> 5;
    const int n0 = blockIdx.x * 128;
    const int m0 = blockIdx.y * 128;
    const int m_w = (w & 3) * 32;
    const int n_w = (w >> 2) * 64;

    float acc[2][8][4];
#pragma unroll
    for (int i = 0; i < 2; i++)
#pragma unroll
        for (int j = 0; j < 8; j++)
#pragma unroll
            for (int q = 0; q < 4; q++) acc[i][j][q] = 0.0f;

    const __nv_bfloat16* srcs[4] = {
        Xhi + (size_t)m0 * 512, Xlo + (size_t)m0 * 512,
        Whi + (size_t)n0 * 512, Wlo + (size_t)n0 * 512 };
    const uint32_t tgt_off[4] = { SM_AHI, SM_ALO, SM_WHI, SM_WLO };

    const int a_row_l = lane & 15;
    const int a_x_l   = (lane >> 4) * 16;
    const int b_row_l = ((lane >> 4) & 1) * 8 + (lane & 7);
    const int b_x_l   = ((lane >> 3) & 1) * 16;

    for (int c = 0; c < 8; c++) {
        const int kc = c * 64;
#pragma unroll
        for (int tgt = 0; tgt < 4; tgt++) {
#pragma unroll
            for (int i = 0; i < 4; i++) {
                const int idx = tid + i * 256;
                const int row = idx >> 3;
                const int cb  = (idx & 7) * 16;
                const char* gp =
                    (const char*)(srcs[tgt] + (size_t)row * 512 + kc) + cb;
                uint4 v = *(const uint4*)gp;
                uint32_t off = (uint32_t)(row * 128 + cb);
                *(uint4*)(sm + tgt_off[tgt] + SWZ128(off)) = v;
            }
        }
        __syncthreads();

#pragma unroll
        for (int sp = 0; sp < 3; sp++) {
            const uint32_t abase = smb + (sp == 1 ? SM_ALO : SM_AHI);
            const uint32_t bbase = smb + (sp == 2 ? SM_WLO : SM_WHI);
#pragma unroll
            for (int ks = 0; ks < 4; ks++) {
                uint32_t afr[2][4];
#pragma unroll
                for (int mb = 0; mb < 2; mb++) {
                    const int row = m_w + mb * 16 + a_row_l;
                    const int x   = a_x_l + ks * 32;
                    uint32_t off = (uint32_t)(row * 128 +
                                              (x ^ ((row & 7) << 4)));
                    ldsm_x4(afr[mb][0], afr[mb][1], afr[mb][2], afr[mb][3],
                            abase + off);
                }
                uint32_t bfr[8][2];
#pragma unroll
                for (int pb = 0; pb < 4; pb++) {
                    const int row = n_w + pb * 16 + b_row_l;
                    const int x   = b_x_l + ks * 32;
                    uint32_t off = (uint32_t)(row * 128 +
                                              (x ^ ((row & 7) << 4)));
                    uint32_t r0, r1, r2, r3;
                    ldsm_x4(r0, r1, r2, r3, bbase + off);
                    bfr[pb * 2 + 0][0] = r0; bfr[pb * 2 + 0][1] = r1;
                    bfr[pb * 2 + 1][0] = r2; bfr[pb * 2 + 1][1] = r3;
                }
#pragma unroll
                for (int mb = 0; mb < 2; mb++)
#pragma unroll
                    for (int nb = 0; nb < 8; nb++)
                        mma16816(acc[mb][nb], afr[mb], bfr[nb]);
            }
        }
        __syncthreads();
    }

    const int rbase = m0 + m_w + (lane >> 2);
    const int cbase = n0 + n_w + (lane & 3) * 2;
#pragma unroll
    for (int mb = 0; mb < 2; mb++) {
#pragma unroll
        for (int nb = 0; nb < 8; nb++) {
            float* p0 = g_xproj + (size_t)(rbase + mb * 16) * 512 + cbase + nb * 8;
            float* p1 = p0 + 8 * 512;
            *(float2*)p0 = make_float2(acc[mb][nb][0], acc[mb][nb][1]);
            *(float2*)p1 = make_float2(acc[mb][nb][2], acc[mb][nb][3]);
        }
    }
}

// ============================================================================
// Kernel 2: recurrent scan via mma.sync, register-resident W_h (R14 base).
// R16 delta: h exchanged as bf16-HI ONLY. Cell u64 = {bf16x2(b0), bf16x2(b1)}
// at [kp][bpair] (kp = k-pair 0..255, bpair 0..3). Producer pushes 2 u64 x 8
// ranks = 16 st.async (was 32); TX 8192 (was 16384). mma: 2 chains (whi,wlo
// vs h_hi), 32 HMMA/warp-step (was 48). W keeps full hi+lo split.
// Layout word index = kp*8 + b  -> lane addr = qb*8 + row_l: conflict-free.
// ============================================================================
#define HC_BUF      8192             // one h buffer: 256 kp x 4 bpair x 8B
#define STG_OFF     (2 * HC_BUF)     // 16384
#define MBAR_OFF2   (STG_OFF + 2048) // 18432
#define SCAN_SMEM   (MBAR_OFF2 + 16)
#define TX_BYTES    8192u

__global__ void __cluster_dims__(8, 1, 1) __launch_bounds__(256, 1)
rnn_scan(const float* __restrict__ Wh, const float* __restrict__ bh,
         float* __restrict__ out) {
    extern __shared__ __align__(16) char sm[];
    char*  hc  = sm;                          // [2][HC_BUF] h cells
    float* stg = (float*)(sm + STG_OFF);      // [4][32] float4 staging

    const int tid   = threadIdx.x;
    const int lane  = tid & 31;
    const int w     = tid >> 5;
    const int j     = w >> 1;        // m-block 0..3
    const int kh    = w & 1;         // k-half
    const int rk    = blockIdx.x & 7;    // cluster rank -> dim slice
    const int g     = blockIdx.x >> 3;   // batch group
    const int row_l = lane >> 2;     // 0..7 (A-row low / B-n = batch)
    const int qb    = lane & 3;

    const uint32_t smb     = (uint32_t)__cvta_generic_to_shared(sm);
    const uint32_t mb_u32  = smb + MBAR_OFF2;

    const int d_base = rk * 64 + j * 16;

    // ---- W_h fragments into registers (bf16 hi/lo split), one-time ----
    uint32_t whi[16][4], wlo[16][4];
    {
        const float* Wr0 = Wh + (size_t)(d_base + row_l) * 512 + kh * 256;
        const float* Wr1 = Wr0 + 8 * 512;
#pragma unroll
        for (int ks = 0; ks < 16; ks++) {
            const int k0 = ks * 16 + qb * 2;
            float2 q00 = *(const float2*)(Wr0 + k0);
            float2 q10 = *(const float2*)(Wr1 + k0);
            float2 q01 = *(const float2*)(Wr0 + k0 + 8);
            float2 q11 = *(const float2*)(Wr1 + k0 + 8);
            split2(q00.x, q00.y, whi[ks][0], wlo[ks][0]);
            split2(q10.x, q10.y, whi[ks][1], wlo[ks][1]);
            split2(q01.x, q01.y, whi[ks][2], wlo[ks][2]);
            split2(q11.x, q11.y, whi[ks][3], wlo[ks][3]);
        }
    }

    // ---- zero h buffer 0 (t=0 reads zeros) ----
    for (int i = tid; i < HC_BUF / 8; i += 256) ((u64*)hc)[i] = 0ull;
    if (tid == 0) {
        mbar_init(mb_u32 + 0, 1);
        mbar_init(mb_u32 + 8, 1);
    }
    __syncthreads();
    asm volatile("barrier.cluster.arrive.aligned;" ::: "memory");
    asm volatile("barrier.cluster.wait.aligned;"   ::: "memory");
    if (tid == 0) {
        mbar_expect_tx(mb_u32 + 0, TX_BYTES);
        mbar_expect_tx(mb_u32 + 8, TX_BYTES);
    }
    asm volatile("barrier.cluster.arrive.aligned;" ::: "memory");
    asm volatile("barrier.cluster.wait.aligned;"   ::: "memory");

    // ---- B-frag read base: u32 at word (kp*8 + batch) ----
    // kp = kh*128 + ks*8 + qb; batch = row_l
    const char* hbase = hc + (size_t)((kh * 128 + qb) * 8 + row_l) * 4;

    // ---- output/push mapping (even warps own final D after reduce) ----
    const int b0l   = qb * 2;                     // local batch pair
    const int bgl0  = g * 8 + b0l;
    const float bias0 = bh[d_base + row_l];
    const float bias1 = bh[d_base + row_l + 8];
    const float* xpb = g_xproj + ((size_t)bgl0 * 512 + d_base + row_l);

    // push destinations: u64 cell (kp=dpA, bpair=qb) in every rank
    const int dpA = rk * 32 + j * 8 + (row_l >> 1);
    const uint32_t cell_off = (uint32_t)(dpA * 32 + qb * 8);
    uint32_t dst[8];
#pragma unroll
    for (int rr = 0; rr < 8; rr++) {
        asm("mapa.shared::cluster.u32 %0, %1, %2;"
            : "=r"(dst[rr]) : "r"(smb + cell_off), "r"(rr));
    }

    // prefetch xp(0)
    float xq0 = 0.f, xq1 = 0.f, xq2 = 0.f, xq3 = 0.f;
    if (!kh) {
        xq0 = __ldg(xpb);        xq1 = __ldg(xpb + 512);
        xq2 = __ldg(xpb + 8);    xq3 = __ldg(xpb + 520);
    }

    uint32_t ph0 = 0, ph1 = 0;

    for (int t = 0; t < T_STEPS; t++) {
        const int p = t & 1;

        if (t > 0) {
            const uint32_t mb = mb_u32 + (uint32_t)p * 8;
            mbar_wait_parity(mb, p ? ph1 : ph0);
            if (p) ph1 ^= 1; else ph0 ^= 1;
            if (tid == 0) mbar_expect_tx(mb, TX_BYTES);
        }

        // ---- mma over this warp's k-half: TWO independent chains ----
        float da[4] = {0.f, 0.f, 0.f, 0.f};   // whi * h_hi
        float db[4] = {0.f, 0.f, 0.f, 0.f};   // wlo * h_hi
        const char* hp = hbase + p * HC_BUF;
#pragma unroll
        for (int ks = 0; ks < 16; ks++) {
            const char* cp = hp + ks * 256;    // ks*8 kp * 32 B/kp
            uint32_t bhv[2];
            bhv[0] = *(const uint32_t*)(cp);
            bhv[1] = *(const uint32_t*)(cp + 128);   // kp+4
            mma16816(da, whi[ks], bhv);
            mma16816(db, wlo[ks], bhv);
        }
        float dacc[4];
#pragma unroll
        for (int q = 0; q < 4; q++) dacc[q] = da[q] + db[q];

        // ---- k-half pair reduce via staging ----
        if (kh) {
            ((float4*)stg)[j * 32 + lane] =
                make_float4(dacc[0], dacc[1], dacc[2], dacc[3]);
        }
        __syncthreads();

        if (!kh) {
            float4 o = ((float4*)stg)[j * 32 + lane];
            const float z0 = dacc[0] + o.x + xq0 + bias0;  // (r,   b0)
            const float z1 = dacc[1] + o.y + xq1 + bias0;  // (r,   b1)
            const float z2 = dacc[2] + o.z + xq2 + bias1;  // (r+8, b0)
            const float z3 = dacc[3] + o.w + xq3 + bias1;
            const float h0 = 1.0f / (1.0f + __expf(-z0));
            const float h1 = 1.0f / (1.0f + __expf(-z1));
            const float h2 = 1.0f / (1.0f + __expf(-z2));
            const float h3 = 1.0f / (1.0f + __expf(-z3));

            if (t < T_STEPS - 1) {
                // partner (d+1) values live at lane+4 (row_l+1)
                const float n0 = __shfl_down_sync(0xffffffffu, h0, 4);
                const float n1 = __shfl_down_sync(0xffffffffu, h1, 4);
                const float n2 = __shfl_down_sync(0xffffffffu, h2, 4);
                const float n3 = __shfl_down_sync(0xffffffffu, h3, 4);
                if (!(row_l & 1)) {
                    // cellA: kp=dpA   holds {(h(d),h(d+1)) b0 | (..) b1}
                    // cellB: kp=dpA+4 (dims d+8, d+9)
                    const u64 cA = pack4bf(h0, n0, h1, n1);
                    const u64 cB = pack4bf(h2, n2, h3, n3);
                    const uint32_t qo = (uint32_t)((p ^ 1) * HC_BUF);
                    const uint32_t mloc = mb_u32 + (uint32_t)((p ^ 1) * 8);
#pragma unroll
                    for (int rr = 0; rr < 8; rr++) {
                        uint32_t m0_;
                        asm("mapa.shared::cluster.u32 %0, %1, %2;"
                            : "=r"(m0_) : "r"(mloc), "r"(rr));
                        const uint32_t d0 = dst[rr] + qo;
                        st_async_cluster_u64(d0, cA, m0_);
                        st_async_cluster_u64(d0 + 128, cB, m0_);  // kp+4
                    }
                }
                // prefetch xp(t+1)
                const float* xn = xpb + (size_t)(t + 1) * BATCH * DIM;
                xq0 = __ldg(xn);      xq1 = __ldg(xn + 512);
                xq2 = __ldg(xn + 8);  xq3 = __ldg(xn + 520);
            } else {
                float* ob = out + (size_t)bgl0 * 512 + d_base + row_l;
                ob[0]       = h0;
                ob[512]     = h1;
                ob[8]       = h2;
                ob[520]     = h3;
            }
        }
    }

    // keep cluster alive for in-flight async stores
    asm volatile("barrier.cluster.arrive.aligned;" ::: "memory");
    asm volatile("barrier.cluster.wait.aligned;"   ::: "memory");
}

// ============================================================================
extern "C" void kernel_launch(void* const* d_in, const int* in_sizes, int n_in,
                              void* d_out, int out_size) {
    const float* X    = (const float*)d_in[0];  // [512,128,512]
    const float* W_in = (const float*)d_in[1];  // [512,512]
    const float* W_h  = (const float*)d_in[2];  // [512,512]
    const float* b_h  = (const float*)d_in[3];  // [512]
    float* out = (float*)d_out;                 // [128,512]

    (void)in_sizes; (void)n_in; (void)out_size;

    __nv_bfloat162 *xhi, *xlo, *whi, *wlo;
    cudaGetSymbolAddress((void**)&xhi, g_Xhi);
    cudaGetSymbolAddress((void**)&xlo, g_Xlo);
    cudaGetSymbolAddress((void**)&whi, g_Whi);
    cudaGetSymbolAddress((void**)&wlo, g_Wlo);

    // 0) split X and W_in into bf16 hi/lo
    split_kernel<<<(M_ROWS * DIM / 4 + 255) / 256, 256>>>(X, xhi, xlo,
                                                          M_ROWS * DIM / 4);
    split_kernel<<<(DIM * DIM / 4 + 255) / 256, 256>>>(W_in, whi, wlo,
                                                       DIM * DIM / 4);

    // 1) Xproj via mma.sync bf16 (3-split)
    cudaFuncSetAttribute(xproj_mma,
                         cudaFuncAttributeMaxDynamicSharedMemorySize,
                         GEMM2_SMEM);
    dim3 g1(DIM / 128, M_ROWS / 128);   // (4, 512)
    xproj_mma<<<g1, 256, GEMM2_SMEM>>>(
        (const __nv_bfloat16*)xhi, (const __nv_bfloat16*)xlo,
        (const __nv_bfloat16*)whi, (const __nv_bfloat16*)wlo);

    // 2) recurrent scan via mma.sync (register-resident W_h, bf16-hi exchange)
    rnn_scan<<<128, 256, SCAN_SMEM>>>(W_h, b_h, out);
}

// round 17
// speedup vs baseline: 2.8008x; 1.0968x over previous
#include <cuda_runtime.h>
#include <cuda_bf16.h>
#include <cstdint>

#define T_STEPS 512
#define BATCH   128
#define DIM     512
#define M_ROWS  (T_STEPS * BATCH)   // 65536

typedef unsigned long long u64;

// Scratch
__device__ float g_xproj[(size_t)T_STEPS * BATCH * DIM];        // 134 MB
__device__ __nv_bfloat16 g_Xhi[(size_t)M_ROWS * DIM];           // 67 MB
__device__ __nv_bfloat16 g_Xlo[(size_t)M_ROWS * DIM];           // 67 MB
__device__ __nv_bfloat16 g_Whi[DIM * DIM];
__device__ __nv_bfloat16 g_Wlo[DIM * DIM];

// ---------------------------------------------------------------------------
// helpers
// ---------------------------------------------------------------------------
__device__ __forceinline__ void split2(float x, float y,
                                       uint32_t& hi, uint32_t& lo) {
    __nv_bfloat16 hx = __float2bfloat16(x), hy = __float2bfloat16(y);
    float rx = x - __bfloat162float(hx);
    float ry = y - __bfloat162float(hy);
    __nv_bfloat162 h2(hx, hy);
    __nv_bfloat162 l2(__float2bfloat16(rx), __float2bfloat16(ry));
    hi = *reinterpret_cast<uint32_t*>(&h2);
    lo = *reinterpret_cast<uint32_t*>(&l2);
}
// pack 4 bf16: {a,b} (batch b0) and {c,d} (batch b1) into one u64
__device__ __forceinline__ u64 pack4bf(float a, float b, float c, float d) {
    __nv_bfloat162 p0(__float2bfloat16(a), __float2bfloat16(b));
    __nv_bfloat162 p1(__float2bfloat16(c), __float2bfloat16(d));
    uint32_t u0 = *reinterpret_cast<uint32_t*>(&p0);
    uint32_t u1 = *reinterpret_cast<uint32_t*>(&p1);
    return (u64)u0 | ((u64)u1 << 32);
}

// mbarrier / st.async (baseline features, proven R9-R16)
__device__ __forceinline__ void mbar_init(uint32_t mb, uint32_t cnt) {
    asm volatile("mbarrier.init.shared.b64 [%0], %1;" :: "r"(mb), "r"(cnt)
                 : "memory");
}
__device__ __forceinline__ void mbar_expect_tx(uint32_t mb, uint32_t bytes) {
    asm volatile("mbarrier.arrive.expect_tx.shared.b64 _, [%0], %1;"
                 :: "r"(mb), "r"(bytes) : "memory");
}
__device__ __forceinline__ void mbar_wait_parity(uint32_t mb, uint32_t par) {
    uint32_t done;
    asm volatile(
        "{\n\t.reg .pred p;\n\t"
        "mbarrier.try_wait.parity.acquire.cta.shared::cta.b64 p, [%1], %2;\n\t"
        "selp.b32 %0, 1, 0, p;\n\t}"
        : "=r"(done) : "r"(mb), "r"(par) : "memory");
    if (!done) {
        asm volatile(
            "{\n\t.reg .pred P1;\n\t"
            "WAIT_LOOP_%=:\n\t"
            "mbarrier.try_wait.parity.acquire.cta.shared::cta.b64 P1, [%0], %1, 0x989680;\n\t"
            "@P1 bra.uni WAIT_DONE_%=;\n\t"
            "bra.uni WAIT_LOOP_%=;\n\t"
            "WAIT_DONE_%=:\n\t}"
            :: "r"(mb), "r"(par) : "memory");
    }
}
__device__ __forceinline__ void st_async_cluster_u64(uint32_t dst, u64 val,
                                                     uint32_t rmb) {
    asm volatile(
        "st.async.shared::cluster.mbarrier::complete_tx::bytes.b64 [%0], %1, [%2];"
        :: "r"(dst), "l"(val), "r"(rmb) : "memory");
}

// cp.async (sm_80 baseline — safe for compute_103)
__device__ __forceinline__ void cp_async16(uint32_t dst, const void* src) {
    asm volatile("cp.async.cg.shared.global [%0], [%1], 16;"
                 :: "r"(dst), "l"(src) : "memory");
}
#define CP_COMMIT() asm volatile("cp.async.commit_group;" ::: "memory")
#define CP_WAIT(n)  asm volatile("cp.async.wait_group %0;" :: "n"(n) : "memory")

// mma.sync / ldmatrix (sm_80+ baseline; validated R11-R16)
__device__ __forceinline__ void ldsm_x4(uint32_t& r0, uint32_t& r1,
                                        uint32_t& r2, uint32_t& r3,
                                        uint32_t addr) {
    asm volatile("ldmatrix.sync.aligned.m8n8.x4.shared.b16 {%0,%1,%2,%3}, [%4];"
                 : "=r"(r0), "=r"(r1), "=r"(r2), "=r"(r3) : "r"(addr));
}
__device__ __forceinline__ void mma16816(float* d, const uint32_t* a,
                                         const uint32_t* b) {
    asm volatile(
        "mma.sync.aligned.m16n8k16.row.col.f32.bf16.bf16.f32 "
        "{%0,%1,%2,%3}, {%4,%5,%6,%7}, {%8,%9}, {%0,%1,%2,%3};"
        : "+f"(d[0]), "+f"(d[1]), "+f"(d[2]), "+f"(d[3])
        : "r"(a[0]), "r"(a[1]), "r"(a[2]), "r"(a[3]), "r"(b[0]), "r"(b[1]));
}
#define SWZ128(o) ((o) ^ (((o) >> 3) & 0x70))

// ============================================================================
// Kernel 0: fp32 -> bf16 hi/lo split
// ============================================================================
__global__ void split_kernel(const float* __restrict__ src,
                             __nv_bfloat162* __restrict__ hi,
                             __nv_bfloat162* __restrict__ lo, int n4) {
    int i = blockIdx.x * 256 + threadIdx.x;
    if (i >= n4) return;
    float4 v = ((const float4*)src)[i];
    uint32_t h0, l0, h1, l1;
    split2(v.x, v.y, h0, l0);
    split2(v.z, v.w, h1, l1);
    *(uint32_t*)&hi[i * 2 + 0] = h0;
    *(uint32_t*)&hi[i * 2 + 1] = h1;
    *(uint32_t*)&lo[i * 2 + 0] = l0;
    *(uint32_t*)&lo[i * 2 + 1] = l1;
}

// ============================================================================
// Kernel 1: Xproj via mma.sync bf16 3-split.
// R17 delta: cp.async DOUBLE-BUFFERED staging (issue chunk c+1 while
// computing chunk c). 2 x 64KB buffers, 1 CTA/SM. Math identical to R16.
// ============================================================================
#define SM_AHI 0
#define SM_ALO 16384
#define SM_WHI 32768
#define SM_WLO 49152
#define GEMM_BUF   65536
#define GEMM2_SMEM (2 * GEMM_BUF)    // 131072

__global__ void __launch_bounds__(256, 1)
xproj_mma(const __nv_bfloat16* __restrict__ Xhi,
          const __nv_bfloat16* __restrict__ Xlo,
          const __nv_bfloat16* __restrict__ Whi,
          const __nv_bfloat16* __restrict__ Wlo) {
    extern __shared__ __align__(1024) char sm[];
    const uint32_t smb = (uint32_t)__cvta_generic_to_shared(sm);
    const int tid  = threadIdx.x;
    const int lane = tid & 31;
    const int w    = tid >> 5;
    const int n0 = blockIdx.x * 128;
    const int m0 = blockIdx.y * 128;
    const int m_w = (w & 3) * 32;
    const int n_w = (w >> 2) * 64;

    float acc[2][8][4];
#pragma unroll
    for (int i = 0; i < 2; i++)
#pragma unroll
        for (int j = 0; j < 8; j++)
#pragma unroll
            for (int q = 0; q < 4; q++) acc[i][j][q] = 0.0f;

    const __nv_bfloat16* srcs[4] = {
        Xhi + (size_t)m0 * 512, Xlo + (size_t)m0 * 512,
        Whi + (size_t)n0 * 512, Wlo + (size_t)n0 * 512 };
    const uint32_t tgt_off[4] = { SM_AHI, SM_ALO, SM_WHI, SM_WLO };

    const int a_row_l = lane & 15;
    const int a_x_l   = (lane >> 4) * 16;
    const int b_row_l = ((lane >> 4) & 1) * 8 + (lane & 7);
    const int b_x_l   = ((lane >> 3) & 1) * 16;

    // -- stage issue: 16 cp.async of 16B per thread into buffer (c&1) --
    auto issue_chunk = [&](int c) {
        const int kc = c * 64;
        const uint32_t bb = smb + (uint32_t)(c & 1) * GEMM_BUF;
#pragma unroll
        for (int tgt = 0; tgt < 4; tgt++) {
#pragma unroll
            for (int i = 0; i < 4; i++) {
                const int idx = tid + i * 256;
                const int row = idx >> 3;
                const int cb  = (idx & 7) * 16;
                const char* gp =
                    (const char*)(srcs[tgt] + (size_t)row * 512 + kc) + cb;
                uint32_t off = (uint32_t)(row * 128 + cb);
                cp_async16(bb + tgt_off[tgt] + SWZ128(off), gp);
            }
        }
        CP_COMMIT();
    };

    issue_chunk(0);

    for (int c = 0; c < 8; c++) {
        if (c < 7) {
            issue_chunk(c + 1);
            CP_WAIT(1);                 // chunk c's group complete
        } else {
            CP_WAIT(0);
        }
        __syncthreads();

        const uint32_t bufb = smb + (uint32_t)(c & 1) * GEMM_BUF;
#pragma unroll
        for (int sp = 0; sp < 3; sp++) {
            const uint32_t abase = bufb + (sp == 1 ? SM_ALO : SM_AHI);
            const uint32_t bbase = bufb + (sp == 2 ? SM_WLO : SM_WHI);
#pragma unroll
            for (int ks = 0; ks < 4; ks++) {
                uint32_t afr[2][4];
#pragma unroll
                for (int mb = 0; mb < 2; mb++) {
                    const int row = m_w + mb * 16 + a_row_l;
                    const int x   = a_x_l + ks * 32;
                    uint32_t off = (uint32_t)(row * 128 +
                                              (x ^ ((row & 7) << 4)));
                    ldsm_x4(afr[mb][0], afr[mb][1], afr[mb][2], afr[mb][3],
                            abase + off);
                }
                uint32_t bfr[8][2];
#pragma unroll
                for (int pb = 0; pb < 4; pb++) {
                    const int row = n_w + pb * 16 + b_row_l;
                    const int x   = b_x_l + ks * 32;
                    uint32_t off = (uint32_t)(row * 128 +
                                              (x ^ ((row & 7) << 4)));
                    uint32_t r0, r1, r2, r3;
                    ldsm_x4(r0, r1, r2, r3, bbase + off);
                    bfr[pb * 2 + 0][0] = r0; bfr[pb * 2 + 0][1] = r1;
                    bfr[pb * 2 + 1][0] = r2; bfr[pb * 2 + 1][1] = r3;
                }
#pragma unroll
                for (int mb = 0; mb < 2; mb++)
#pragma unroll
                    for (int nb = 0; nb < 8; nb++)
                        mma16816(acc[mb][nb], afr[mb], bfr[nb]);
            }
        }
        __syncthreads();   // all reads of buf[c&1] done before its refill
    }

    const int rbase = m0 + m_w + (lane >> 2);
    const int cbase = n0 + n_w + (lane & 3) * 2;
#pragma unroll
    for (int mb = 0; mb < 2; mb++) {
#pragma unroll
        for (int nb = 0; nb < 8; nb++) {
            float* p0 = g_xproj + (size_t)(rbase + mb * 16) * 512 + cbase + nb * 8;
            float* p1 = p0 + 8 * 512;
            *(float2*)p0 = make_float2(acc[mb][nb][0], acc[mb][nb][1]);
            *(float2*)p1 = make_float2(acc[mb][nb][2], acc[mb][nb][3]);
        }
    }
}

// ============================================================================
// Kernel 2: recurrent scan — BYTE-IDENTICAL to R16 (golden: 1.01 ms).
// Register-resident W_h (hi/lo), bf16-hi h exchange via st.async + mbarrier.
// ============================================================================
#define HC_BUF      8192             // one h buffer: 256 kp x 4 bpair x 8B
#define STG_OFF     (2 * HC_BUF)     // 16384
#define MBAR_OFF2   (STG_OFF + 2048) // 18432
#define SCAN_SMEM   (MBAR_OFF2 + 16)
#define TX_BYTES    8192u

__global__ void __cluster_dims__(8, 1, 1) __launch_bounds__(256, 1)
rnn_scan(const float* __restrict__ Wh, const float* __restrict__ bh,
         float* __restrict__ out) {
    extern __shared__ __align__(16) char sm[];
    char*  hc  = sm;                          // [2][HC_BUF] h cells
    float* stg = (float*)(sm + STG_OFF);      // [4][32] float4 staging

    const int tid   = threadIdx.x;
    const int lane  = tid & 31;
    const int w     = tid >> 5;
    const int j     = w >> 1;        // m-block 0..3
    const int kh    = w & 1;         // k-half
    const int rk    = blockIdx.x & 7;    // cluster rank -> dim slice
    const int g     = blockIdx.x >> 3;   // batch group
    const int row_l = lane >> 2;     // 0..7 (A-row low / B-n = batch)
    const int qb    = lane & 3;

    const uint32_t smb     = (uint32_t)__cvta_generic_to_shared(sm);
    const uint32_t mb_u32  = smb + MBAR_OFF2;

    const int d_base = rk * 64 + j * 16;

    // ---- W_h fragments into registers (bf16 hi/lo split), one-time ----
    uint32_t whi[16][4], wlo[16][4];
    {
        const float* Wr0 = Wh + (size_t)(d_base + row_l) * 512 + kh * 256;
        const float* Wr1 = Wr0 + 8 * 512;
#pragma unroll
        for (int ks = 0; ks < 16; ks++) {
            const int k0 = ks * 16 + qb * 2;
            float2 q00 = *(const float2*)(Wr0 + k0);
            float2 q10 = *(const float2*)(Wr1 + k0);
            float2 q01 = *(const float2*)(Wr0 + k0 + 8);
            float2 q11 = *(const float2*)(Wr1 + k0 + 8);
            split2(q00.x, q00.y, whi[ks][0], wlo[ks][0]);
            split2(q10.x, q10.y, whi[ks][1], wlo[ks][1]);
            split2(q01.x, q01.y, whi[ks][2], wlo[ks][2]);
            split2(q11.x, q11.y, whi[ks][3], wlo[ks][3]);
        }
    }

    // ---- zero h buffer 0 (t=0 reads zeros) ----
    for (int i = tid; i < HC_BUF / 8; i += 256) ((u64*)hc)[i] = 0ull;
    if (tid == 0) {
        mbar_init(mb_u32 + 0, 1);
        mbar_init(mb_u32 + 8, 1);
    }
    __syncthreads();
    asm volatile("barrier.cluster.arrive.aligned;" ::: "memory");
    asm volatile("barrier.cluster.wait.aligned;"   ::: "memory");
    if (tid == 0) {
        mbar_expect_tx(mb_u32 + 0, TX_BYTES);
        mbar_expect_tx(mb_u32 + 8, TX_BYTES);
    }
    asm volatile("barrier.cluster.arrive.aligned;" ::: "memory");
    asm volatile("barrier.cluster.wait.aligned;"   ::: "memory");

    // ---- B-frag read base: u32 at word (kp*8 + batch) ----
    const char* hbase = hc + (size_t)((kh * 128 + qb) * 8 + row_l) * 4;

    // ---- output/push mapping (even warps own final D after reduce) ----
    const int b0l   = qb * 2;                     // local batch pair
    const int bgl0  = g * 8 + b0l;
    const float bias0 = bh[d_base + row_l];
    const float bias1 = bh[d_base + row_l + 8];
    const float* xpb = g_xproj + ((size_t)bgl0 * 512 + d_base + row_l);

    // push destinations: u64 cell (kp=dpA, bpair=qb) in every rank
    const int dpA = rk * 32 + j * 8 + (row_l >> 1);
    const uint32_t cell_off = (uint32_t)(dpA * 32 + qb * 8);
    uint32_t dst[8];
#pragma unroll
    for (int rr = 0; rr < 8; rr++) {
        asm("mapa.shared::cluster.u32 %0, %1, %2;"
            : "=r"(dst[rr]) : "r"(smb + cell_off), "r"(rr));
    }

    // prefetch xp(0)
    float xq0 = 0.f, xq1 = 0.f, xq2 = 0.f, xq3 = 0.f;
    if (!kh) {
        xq0 = __ldg(xpb);        xq1 = __ldg(xpb + 512);
        xq2 = __ldg(xpb + 8);    xq3 = __ldg(xpb + 520);
    }

    uint32_t ph0 = 0, ph1 = 0;

    for (int t = 0; t < T_STEPS; t++) {
        const int p = t & 1;

        if (t > 0) {
            const uint32_t mb = mb_u32 + (uint32_t)p * 8;
            mbar_wait_parity(mb, p ? ph1 : ph0);
            if (p) ph1 ^= 1; else ph0 ^= 1;
            if (tid == 0) mbar_expect_tx(mb, TX_BYTES);
        }

        // ---- mma over this warp's k-half: TWO independent chains ----
        float da[4] = {0.f, 0.f, 0.f, 0.f};   // whi * h_hi
        float db[4] = {0.f, 0.f, 0.f, 0.f};   // wlo * h_hi
        const char* hp = hbase + p * HC_BUF;
#pragma unroll
        for (int ks = 0; ks < 16; ks++) {
            const char* cp = hp + ks * 256;    // ks*8 kp * 32 B/kp
            uint32_t bhv[2];
            bhv[0] = *(const uint32_t*)(cp);
            bhv[1] = *(const uint32_t*)(cp + 128);   // kp+4
            mma16816(da, whi[ks], bhv);
            mma16816(db, wlo[ks], bhv);
        }
        float dacc[4];
#pragma unroll
        for (int q = 0; q < 4; q++) dacc[q] = da[q] + db[q];

        // ---- k-half pair reduce via staging ----
        if (kh) {
            ((float4*)stg)[j * 32 + lane] =
                make_float4(dacc[0], dacc[1], dacc[2], dacc[3]);
        }
        __syncthreads();

        if (!kh) {
            float4 o = ((float4*)stg)[j * 32 + lane];
            const float z0 = dacc[0] + o.x + xq0 + bias0;  // (r,   b0)
            const float z1 = dacc[1] + o.y + xq1 + bias0;  // (r,   b1)
            const float z2 = dacc[2] + o.z + xq2 + bias1;  // (r+8, b0)
            const float z3 = dacc[3] + o.w + xq3 + bias1;
            const float h0 = 1.0f / (1.0f + __expf(-z0));
            const float h1 = 1.0f / (1.0f + __expf(-z1));
            const float h2 = 1.0f / (1.0f + __expf(-z2));
            const float h3 = 1.0f / (1.0f + __expf(-z3));

            if (t < T_STEPS - 1) {
                // partner (d+1) values live at lane+4 (row_l+1)
                const float n0 = __shfl_down_sync(0xffffffffu, h0, 4);
                const float n1 = __shfl_down_sync(0xffffffffu, h1, 4);
                const float n2 = __shfl_down_sync(0xffffffffu, h2, 4);
                const float n3 = __shfl_down_sync(0xffffffffu, h3, 4);
                if (!(row_l & 1)) {
                    const u64 cA = pack4bf(h0, n0, h1, n1);
                    const u64 cB = pack4bf(h2, n2, h3, n3);
                    const uint32_t qo = (uint32_t)((p ^ 1) * HC_BUF);
                    const uint32_t mloc = mb_u32 + (uint32_t)((p ^ 1) * 8);
#pragma unroll
                    for (int rr = 0; rr < 8; rr++) {
                        uint32_t m0_;
                        asm("mapa.shared::cluster.u32 %0, %1, %2;"
                            : "=r"(m0_) : "r"(mloc), "r"(rr));
                        const uint32_t d0 = dst[rr] + qo;
                        st_async_cluster_u64(d0, cA, m0_);
                        st_async_cluster_u64(d0 + 128, cB, m0_);  // kp+4
                    }
                }
                // prefetch xp(t+1)
                const float* xn = xpb + (size_t)(t + 1) * BATCH * DIM;
                xq0 = __ldg(xn);      xq1 = __ldg(xn + 512);
                xq2 = __ldg(xn + 8);  xq3 = __ldg(xn + 520);
            } else {
                float* ob = out + (size_t)bgl0 * 512 + d_base + row_l;
                ob[0]       = h0;
                ob[512]     = h1;
                ob[8]       = h2;
                ob[520]     = h3;
            }
        }
    }

    // keep cluster alive for in-flight async stores
    asm volatile("barrier.cluster.arrive.aligned;" ::: "memory");
    asm volatile("barrier.cluster.wait.aligned;"   ::: "memory");
}

// ============================================================================
extern "C" void kernel_launch(void* const* d_in, const int* in_sizes, int n_in,
                              void* d_out, int out_size) {
    const float* X    = (const float*)d_in[0];  // [512,128,512]
    const float* W_in = (const float*)d_in[1];  // [512,512]
    const float* W_h  = (const float*)d_in[2];  // [512,512]
    const float* b_h  = (const float*)d_in[3];  // [512]
    float* out = (float*)d_out;                 // [128,512]

    (void)in_sizes; (void)n_in; (void)out_size;

    __nv_bfloat162 *xhi, *xlo, *whi, *wlo;
    cudaGetSymbolAddress((void**)&xhi, g_Xhi);
    cudaGetSymbolAddress((void**)&xlo, g_Xlo);
    cudaGetSymbolAddress((void**)&whi, g_Whi);
    cudaGetSymbolAddress((void**)&wlo, g_Wlo);

    // 0) split X and W_in into bf16 hi/lo
    split_kernel<<<(M_ROWS * DIM / 4 + 255) / 256, 256>>>(X, xhi, xlo,
                                                          M_ROWS * DIM / 4);
    split_kernel<<<(DIM * DIM / 4 + 255) / 256, 256>>>(W_in, whi, wlo,
                                                       DIM * DIM / 4);

    // 1) Xproj via mma.sync bf16 (3-split), cp.async double-buffered
    cudaFuncSetAttribute(xproj_mma,
                         cudaFuncAttributeMaxDynamicSharedMemorySize,
                         GEMM2_SMEM);
    dim3 g1(DIM / 128, M_ROWS / 128);   // (4, 512)
    xproj_mma<<<g1, 256, GEMM2_SMEM>>>(
        (const __nv_bfloat16*)xhi, (const __nv_bfloat16*)xlo,
        (const __nv_bfloat16*)whi, (const __nv_bfloat16*)wlo);

    // 2) recurrent scan — unchanged R16
    rnn_scan<<<128, 256, SCAN_SMEM>>>(W_h, b_h, out);
}